// round 4
// baseline (speedup 1.0000x reference)
#include <cuda_runtime.h>
#include <cuda_bf16.h>
#include <cstdint>

// Problem constants
#define B      64
#define T      512
#define DIM    512
#define VOCAB  32000

// ---------------- device scratch (no allocation allowed) ----------------
__device__ float    g_xp [(size_t)T * B * DIM];   // [t][b][h]  67MB
__device__ float    g_hid[(size_t)T * B * DIM];   // [t][b][h]  67MB
__device__ float    g_hbuf[2 * B * DIM];          // double-buffered h state
__device__ unsigned g_bar[T * 16];                // per-step per-group barrier

// ---------------- packed fp32x2 FMA (Blackwell FFMA2) ----------------
__device__ __forceinline__ void fma2(unsigned long long &d,
                                     unsigned long long a,
                                     unsigned long long b) {
    asm("fma.rn.f32x2 %0, %1, %2, %0;" : "+l"(d) : "l"(a), "l"(b));
}
__device__ __forceinline__ float sum2(unsigned long long v) {
    return __uint_as_float((unsigned)v) + __uint_as_float((unsigned)(v >> 32));
}

// =====================================================================
// Kernel 1: xp[t][b][h] = emb[x[b][t]] . W_ih[h] + b_ih[h] + b_hh[h]
// 128x128x16 tile GEMM, 256 threads, 8x8 register blocking.
// =====================================================================
#define GBM 128
#define GBN 128
#define GBK 16

__global__ __launch_bounds__(256) void gemm_xp_kernel(
    const int* __restrict__ x, const float* __restrict__ emb,
    const float* __restrict__ W_ih, const float* __restrict__ b_ih,
    const float* __restrict__ b_hh)
{
    __shared__ float As[GBM][GBK + 1];
    __shared__ float Bs[GBN][GBK + 1];
    __shared__ int   idxs[GBM];
    __shared__ float bias[GBN];

    const int tid = threadIdx.x;
    const int tx = tid & 15, ty = tid >> 4;
    const int m0 = blockIdx.y * GBM;        // m = t*64 + b
    const int n0 = blockIdx.x * GBN;

    if (tid < GBM) {
        int m = m0 + tid;
        int bb = m & 63, tt = m >> 6;
        idxs[tid] = x[bb * T + tt];
        bias[tid] = b_ih[n0 + tid] + b_hh[n0 + tid];
    }
    __syncthreads();

    float acc[8][8];
#pragma unroll
    for (int i = 0; i < 8; ++i)
#pragma unroll
        for (int j = 0; j < 8; ++j) acc[i][j] = 0.0f;

    const float4* emb4 = reinterpret_cast<const float4*>(emb);
    const float4* wih4 = reinterpret_cast<const float4*>(W_ih);

    for (int k0 = 0; k0 < DIM; k0 += GBK) {
        // load A (gathered emb rows) and B (W_ih rows): 2x float4 each
        float4 av[2], bv[2];
        int mmv[2], kqv[2];
#pragma unroll
        for (int r = 0; r < 2; ++r) {
            int f = r * 256 + tid;          // 0..511
            int mm = f >> 2, kq = f & 3;
            mmv[r] = mm; kqv[r] = kq;
            av[r] = __ldg(&emb4[(size_t)idxs[mm] * (DIM / 4) + (k0 >> 2) + kq]);
            bv[r] = __ldg(&wih4[(size_t)(n0 + mm) * (DIM / 4) + (k0 >> 2) + kq]);
        }
        __syncthreads();   // previous compute done before overwriting tiles
#pragma unroll
        for (int r = 0; r < 2; ++r) {
            int mm = mmv[r], kc = kqv[r] * 4;
            As[mm][kc + 0] = av[r].x; As[mm][kc + 1] = av[r].y;
            As[mm][kc + 2] = av[r].z; As[mm][kc + 3] = av[r].w;
            Bs[mm][kc + 0] = bv[r].x; Bs[mm][kc + 1] = bv[r].y;
            Bs[mm][kc + 2] = bv[r].z; Bs[mm][kc + 3] = bv[r].w;
        }
        __syncthreads();

#pragma unroll
        for (int kk = 0; kk < GBK; ++kk) {
            float a[8], b[8];
#pragma unroll
            for (int r = 0; r < 8; ++r) {
                a[r] = As[ty + 16 * r][kk];
                b[r] = Bs[tx + 16 * r][kk];
            }
#pragma unroll
            for (int i = 0; i < 8; ++i)
#pragma unroll
                for (int j = 0; j < 8; ++j)
                    acc[i][j] = fmaf(a[i], b[j], acc[i][j]);
        }
    }
    __syncthreads();

#pragma unroll
    for (int i = 0; i < 8; ++i) {
        int m = m0 + ty + 16 * i;
#pragma unroll
        for (int j = 0; j < 8; ++j) {
            int nn = tx + 16 * j;
            g_xp[(size_t)m * DIM + n0 + nn] = acc[i][j] + bias[nn];
        }
    }
}

// =====================================================================
// Kernel 2: persistent RNN recurrence.
// Grid: (8 h-slices, 16 batch-groups) = 128 CTAs, all co-resident.
// Each CTA: 4 batches x 64 h rows; W_hh slice (128KB) resident in smem.
// Per-step: load h from L2 (__ldcg), matvec with f32x2, tanh, publish,
// spin-barrier among the 8 slices of the group.
// =====================================================================
#define RNN_GROUPS 16
#define RNN_SLICES 8
#define RNN_B 4
#define RNN_H 64
#define RNN_SMEM (RNN_H*DIM*4 + RNN_B*DIM*4 + 4*RNN_B*RNN_H*4)  // 143360

__global__ __launch_bounds__(256, 1) void rnn_kernel(const float* __restrict__ W_hh)
{
    extern __shared__ __align__(16) unsigned char smem_raw[];
    float* Wsm  = (float*)smem_raw;                 // 64*512
    float* hsm  = Wsm + RNN_H * DIM;                // 4*512
    float* part = hsm + RNN_B * DIM;                // 4*4*64

    const int tid   = threadIdx.x;
    const int slice = blockIdx.x;
    const int g     = blockIdx.y;
    const int hs0   = slice * RNN_H;
    const int b0    = g * RNN_B;

    // --- load W slice into smem (contiguous copy, layout [h][j]) ---
    {
        const float4* Wg4 = reinterpret_cast<const float4*>(W_hh)
                            + (size_t)hs0 * (DIM / 4);
        float4* Wsm4 = (float4*)Wsm;
#pragma unroll
        for (int r = 0; r < (RNN_H * DIM / 4) / 256; ++r)   // 32 iters
            Wsm4[r * 256 + tid] = __ldg(&Wg4[r * 256 + tid]);
    }

    const ulonglong2* W2 = (const ulonglong2*)Wsm;   // 128 x 16B per row
    const ulonglong2* H2 = (const ulonglong2*)hsm;
    float4* hsm4 = (float4*)hsm;

    const int h     = tid & 63;
    const int js    = tid >> 6;
    const int mask  = h & 7;
    const int cbase = js * 32;
    const int fb    = tid >> 6;     // final-stage batch
    const int fh    = tid & 63;     // final-stage h

    __syncthreads();

    for (int t = 0; t < T; ++t) {
        // ---- load h_prev (L2-coherent) into smem ----
        const float4* hb4 = reinterpret_cast<const float4*>(g_hbuf)
                            + (size_t)(t & 1) * (B * DIM / 4);
#pragma unroll
        for (int r = 0; r < 2; ++r) {
            int f = r * 256 + tid;          // 0..511
            int bb = f >> 7, c = f & 127;
            hsm4[bb * 128 + c] = __ldcg(&hb4[(size_t)(b0 + bb) * 128 + c]);
        }
        __syncthreads();

        // ---- matvec: thread (h, js) does 1/4 of 4 dot products ----
        unsigned long long a0x=0,a0y=0,a1x=0,a1y=0,a2x=0,a2y=0,a3x=0,a3y=0;
        const ulonglong2* Wr = W2 + h * 128;
#pragma unroll 8
        for (int i = 0; i < 32; ++i) {
            int c = cbase + (i ^ mask);     // XOR order -> conflict-free LDS
            ulonglong2 w  = Wr[c];
            ulonglong2 x0 = H2[c];
            fma2(a0x, w.x, x0.x); fma2(a0y, w.y, x0.y);
            ulonglong2 x1 = H2[128 + c];
            fma2(a1x, w.x, x1.x); fma2(a1y, w.y, x1.y);
            ulonglong2 x2 = H2[256 + c];
            fma2(a2x, w.x, x2.x); fma2(a2y, w.y, x2.y);
            ulonglong2 x3 = H2[384 + c];
            fma2(a3x, w.x, x3.x); fma2(a3y, w.y, x3.y);
        }
        part[(js * 4 + 0) * 64 + h] = sum2(a0x) + sum2(a0y);
        part[(js * 4 + 1) * 64 + h] = sum2(a1x) + sum2(a1y);
        part[(js * 4 + 2) * 64 + h] = sum2(a2x) + sum2(a2y);
        part[(js * 4 + 3) * 64 + h] = sum2(a3x) + sum2(a3y);
        __syncthreads();

        // ---- reduce 4 partials, add xp, tanh, publish ----
        float dot = part[(0 * 4 + fb) * 64 + fh]
                  + part[(1 * 4 + fb) * 64 + fh]
                  + part[(2 * 4 + fb) * 64 + fh]
                  + part[(3 * 4 + fb) * 64 + fh];
        float val = dot + __ldg(&g_xp[((size_t)t * B + (b0 + fb)) * DIM + hs0 + fh]);
        float hn = tanhf(val);
        g_hbuf[(size_t)((t + 1) & 1) * B * DIM + (size_t)(b0 + fb) * DIM + hs0 + fh] = hn;
        g_hid[((size_t)t * B + (b0 + fb)) * DIM + hs0 + fh] = hn;

        // ---- barrier among the 8 slice-CTAs of this group ----
        __threadfence();        // publish this thread's stores (release)
        __syncthreads();
        if (tid == 0) {
            unsigned* bar = &g_bar[t * RNN_GROUPS + g];
            atomicAdd(bar, 1u);
            while (*((volatile unsigned*)bar) < RNN_SLICES) { __nanosleep(32); }
            __threadfence();    // acquire
        }
        __syncthreads();
    }
}

// =====================================================================
// Kernel 3: softmax over H (axis=1 of [B,H,T]) + transpose [t][b][h] -> [b][h][t]
// Grid: (32 t-tiles of 16, 64 batches), 256 threads.
// =====================================================================
__global__ __launch_bounds__(256) void softmax_kernel(float* __restrict__ out)
{
    __shared__ float tile[16][513];
    __shared__ float rinv[16];

    const int tid = threadIdx.x;
    const int bb  = blockIdx.y;
    const int t0  = blockIdx.x * 16;

    // load 16 rows of [b][:] (coalesced in h)
#pragma unroll
    for (int it = 0; it < 32; ++it) {
        int f = it * 256 + tid;             // 0..8191
        int tt = f >> 9, hh = f & 511;
        tile[tt][hh] = __ldg(&g_hid[((size_t)(t0 + tt) * B + bb) * DIM + hh]);
    }
    __syncthreads();

    // per-row max + exp + sum (warp w -> rows 2w, 2w+1)
    const int wid = tid >> 5, lane = tid & 31;
#pragma unroll
    for (int rr = 0; rr < 2; ++rr) {
        int tt = wid * 2 + rr;
        float m = -3.4e38f;
#pragma unroll
        for (int k = 0; k < 16; ++k) m = fmaxf(m, tile[tt][lane + 32 * k]);
#pragma unroll
        for (int off = 16; off >= 1; off >>= 1)
            m = fmaxf(m, __shfl_xor_sync(0xffffffffu, m, off));
        float s = 0.0f;
#pragma unroll
        for (int k = 0; k < 16; ++k) {
            float e = __expf(tile[tt][lane + 32 * k] - m);
            tile[tt][lane + 32 * k] = e;
            s += e;
        }
#pragma unroll
        for (int off = 16; off >= 1; off >>= 1)
            s += __shfl_xor_sync(0xffffffffu, s, off);
        if (lane == 0) rinv[tt] = 1.0f / s;
    }
    __syncthreads();

    // transpose-write: half-warp lanes = 16 consecutive t -> coalesced
    const int hw  = tid >> 4;     // 0..15
    const int l16 = tid & 15;     // tt
#pragma unroll
    for (int it = 0; it < 32; ++it) {
        int hh = it * 16 + hw;
        float v = tile[l16][hh] * rinv[l16];
        out[((size_t)bb * DIM + hh) * T + t0 + l16] = v;
    }
}

// =====================================================================
extern "C" void kernel_launch(void* const* d_in, const int* in_sizes, int n_in,
                              void* d_out, int out_size)
{
    const int*   x    = (const int*)  d_in[0];
    const float* emb  = (const float*)d_in[1];
    const float* W_ih = (const float*)d_in[2];
    const float* W_hh = (const float*)d_in[3];
    const float* b_ih = (const float*)d_in[4];
    const float* b_hh = (const float*)d_in[5];
    float* out = (float*)d_out;

    void *p_hbuf, *p_bar;
    cudaGetSymbolAddress(&p_hbuf, g_hbuf);
    cudaGetSymbolAddress(&p_bar,  g_bar);
    cudaMemsetAsync(p_hbuf, 0, sizeof(float) * 2 * B * DIM);
    cudaMemsetAsync(p_bar,  0, sizeof(unsigned) * T * 16);

    cudaFuncSetAttribute(rnn_kernel,
                         cudaFuncAttributeMaxDynamicSharedMemorySize, RNN_SMEM);

    // 1) input projection GEMM -> g_xp
    gemm_xp_kernel<<<dim3(DIM / GBN, (T * B) / GBM), 256>>>(x, emb, W_ih, b_ih, b_hh);

    // 2) persistent recurrence -> g_hid
    rnn_kernel<<<dim3(RNN_SLICES, RNN_GROUPS), 256, RNN_SMEM>>>(W_hh);

    // 3) softmax over H + transpose -> out
    softmax_kernel<<<dim3(T / 16, B), 256>>>(out);
}

// round 5
// speedup vs baseline: 1.1132x; 1.1132x over previous
#include <cuda_runtime.h>
#include <cuda_bf16.h>
#include <cstdint>

// Problem constants
#define B      64
#define T      512
#define DIM    512
#define VOCAB  32000

// ---------------- device scratch (no allocation allowed) ----------------
__device__ float    g_xp [(size_t)T * B * DIM];   // [t][b][h]  67MB
__device__ float    g_hid[(size_t)T * B * DIM];   // [t][b][h]  67MB
__device__ float    g_hbuf[2 * B * DIM];          // double-buffered h state
__device__ unsigned g_bar[T * 16];                // per-step per-group barrier

// ---------------- packed fp32x2 FMA (Blackwell FFMA2) ----------------
__device__ __forceinline__ void fma2(unsigned long long &d,
                                     unsigned long long a,
                                     unsigned long long b) {
    asm("fma.rn.f32x2 %0, %1, %2, %0;" : "+l"(d) : "l"(a), "l"(b));
}
__device__ __forceinline__ float sum2(unsigned long long v) {
    return __uint_as_float((unsigned)v) + __uint_as_float((unsigned)(v >> 32));
}
__device__ __forceinline__ unsigned long long pack2(float a) {
    unsigned long long r;
    asm("mov.b64 %0, {%1, %1};" : "=l"(r) : "f"(a));
    return r;
}
__device__ __forceinline__ float lo32(unsigned long long v) {
    return __uint_as_float((unsigned)v);
}
__device__ __forceinline__ float hi32(unsigned long long v) {
    return __uint_as_float((unsigned)(v >> 32));
}

// =====================================================================
// Kernel 1: xp[t][b][h] = emb[x[b][t]] . W_ih[h] + b_ih[h] + b_hh[h]
// 128x128x16 tile GEMM, 256 threads, 8x8 register blocking.
// k-major smem tiles -> float4 LDS for register tiles; f32x2 accumulate.
// =====================================================================
#define GBM 128
#define GBN 128
#define GBK 16
#define GLD 132   // k-major row stride (floats), padded

__global__ __launch_bounds__(256) void gemm_xp_kernel(
    const int* __restrict__ x, const float* __restrict__ emb,
    const float* __restrict__ W_ih, const float* __restrict__ b_ih,
    const float* __restrict__ b_hh)
{
    __shared__ float As[GBK][GLD];   // [k][m]
    __shared__ float Bs[GBK][GLD];   // [k][n]
    __shared__ int   idxs[GBM];
    __shared__ float bias[GBN];

    const int tid = threadIdx.x;
    const int tx = tid & 15, ty = tid >> 4;
    const int m0 = blockIdx.y * GBM;        // m = t*64 + b
    const int n0 = blockIdx.x * GBN;

    if (tid < GBM) {
        int m = m0 + tid;
        int bb = m & 63, tt = m >> 6;
        idxs[tid] = x[bb * T + tt];
        bias[tid] = b_ih[n0 + tid] + b_hh[n0 + tid];
    }
    __syncthreads();

    unsigned long long acc[8][4];
#pragma unroll
    for (int i = 0; i < 8; ++i)
#pragma unroll
        for (int j = 0; j < 4; ++j) acc[i][j] = 0ull;

    const float4* emb4 = reinterpret_cast<const float4*>(emb);
    const float4* wih4 = reinterpret_cast<const float4*>(W_ih);

    for (int k0 = 0; k0 < DIM; k0 += GBK) {
        // load A (gathered emb rows) and B (W_ih rows): 2x float4 each
        float4 av[2], bv[2];
        int mmv[2], kqv[2];
#pragma unroll
        for (int r = 0; r < 2; ++r) {
            int f = r * 256 + tid;          // 0..511
            int mm = f >> 2, kq = f & 3;
            mmv[r] = mm; kqv[r] = kq;
            av[r] = __ldg(&emb4[(size_t)idxs[mm] * (DIM / 4) + (k0 >> 2) + kq]);
            bv[r] = __ldg(&wih4[(size_t)(n0 + mm) * (DIM / 4) + (k0 >> 2) + kq]);
        }
        __syncthreads();   // previous compute done before overwriting tiles
#pragma unroll
        for (int r = 0; r < 2; ++r) {
            int mm = mmv[r], kc = kqv[r] * 4;
            As[kc + 0][mm] = av[r].x; As[kc + 1][mm] = av[r].y;
            As[kc + 2][mm] = av[r].z; As[kc + 3][mm] = av[r].w;
            Bs[kc + 0][mm] = bv[r].x; Bs[kc + 1][mm] = bv[r].y;
            Bs[kc + 2][mm] = bv[r].z; Bs[kc + 3][mm] = bv[r].w;
        }
        __syncthreads();

#pragma unroll
        for (int kk = 0; kk < GBK; ++kk) {
            float4 a0 = *reinterpret_cast<const float4*>(&As[kk][ty * 4]);
            float4 a1 = *reinterpret_cast<const float4*>(&As[kk][64 + ty * 4]);
            float4 b0 = *reinterpret_cast<const float4*>(&Bs[kk][tx * 4]);
            float4 b1 = *reinterpret_cast<const float4*>(&Bs[kk][64 + tx * 4]);
            ulonglong2 bp0 = *reinterpret_cast<ulonglong2*>(&b0);
            ulonglong2 bp1 = *reinterpret_cast<ulonglong2*>(&b1);
            float avv[8] = {a0.x, a0.y, a0.z, a0.w, a1.x, a1.y, a1.z, a1.w};
#pragma unroll
            for (int i = 0; i < 8; ++i) {
                unsigned long long ap = pack2(avv[i]);
                fma2(acc[i][0], ap, bp0.x);
                fma2(acc[i][1], ap, bp0.y);
                fma2(acc[i][2], ap, bp1.x);
                fma2(acc[i][3], ap, bp1.y);
            }
        }
    }

    float4 bs0 = *reinterpret_cast<const float4*>(&bias[tx * 4]);
    float4 bs1 = *reinterpret_cast<const float4*>(&bias[64 + tx * 4]);
#pragma unroll
    for (int i = 0; i < 8; ++i) {
        int m = m0 + ((i < 4) ? (ty * 4 + i) : (64 + ty * 4 + (i - 4)));
        float4 o0, o1;
        o0.x = lo32(acc[i][0]) + bs0.x;  o0.y = hi32(acc[i][0]) + bs0.y;
        o0.z = lo32(acc[i][1]) + bs0.z;  o0.w = hi32(acc[i][1]) + bs0.w;
        o1.x = lo32(acc[i][2]) + bs1.x;  o1.y = hi32(acc[i][2]) + bs1.y;
        o1.z = lo32(acc[i][3]) + bs1.z;  o1.w = hi32(acc[i][3]) + bs1.w;
        *reinterpret_cast<float4*>(&g_xp[(size_t)m * DIM + n0 + tx * 4])      = o0;
        *reinterpret_cast<float4*>(&g_xp[(size_t)m * DIM + n0 + 64 + tx * 4]) = o1;
    }
}

// =====================================================================
// Kernel 2: persistent RNN recurrence. W_hh resident in REGISTERS.
// Grid: (8 h-slices, 16 batch-groups) = 128 CTAs, all co-resident.
// Thread (h=tid&63, js=tid>>6) owns W_hh[hs0+h][js*128 : js*128+128] in
// 64 f32x2 registers. js is warp-uniform -> every H smem read is a
// broadcast (uniform address) LDS.128.
// =====================================================================
#define RNN_GROUPS 16
#define RNN_SLICES 8
#define RNN_B 4
#define RNN_H 64

__global__ __launch_bounds__(256, 1) void rnn_kernel(const float* __restrict__ W_hh)
{
    __shared__ float hsm[RNN_B * DIM];            // 8KB: h state [b][j]
    __shared__ float part[4 * RNN_B * RNN_H];     // 4KB: [js][b][h]

    const int tid   = threadIdx.x;
    const int slice = blockIdx.x;
    const int g     = blockIdx.y;
    const int hs0   = slice * RNN_H;
    const int b0    = g * RNN_B;
    const int h     = tid & 63;
    const int js    = tid >> 6;      // warp-uniform (2 warps per js)

    // --- load this thread's W row-segment into registers (f32x2 packed) ---
    unsigned long long w[64];
    {
        const float4* Wg4 = reinterpret_cast<const float4*>(W_hh)
                            + (size_t)(hs0 + h) * (DIM / 4) + js * 32;
#pragma unroll
        for (int k = 0; k < 32; ++k) {
            float4 v = __ldg(&Wg4[k]);
            ulonglong2 p = *reinterpret_cast<ulonglong2*>(&v);
            w[2 * k]     = p.x;
            w[2 * k + 1] = p.y;
        }
    }

    const ulonglong2* H2 = reinterpret_cast<const ulonglong2*>(hsm);  // [b*128 + c]
    float4* hsm4 = reinterpret_cast<float4*>(hsm);
    const int cbase = js * 32;

    __syncthreads();

    for (int t = 0; t < T; ++t) {
        // ---- prefetch xp for this thread's output element ----
        float xpv = __ldg(&g_xp[((size_t)t * B + (b0 + js)) * DIM + hs0 + h]);

        // ---- load h_prev (L2-coherent) into smem ----
        const float4* hb4 = reinterpret_cast<const float4*>(g_hbuf)
                            + (size_t)(t & 1) * (B * DIM / 4);
#pragma unroll
        for (int r = 0; r < 2; ++r) {
            int f = r * 256 + tid;          // 0..511
            int bb = f >> 7, c = f & 127;
            hsm4[bb * 128 + c] = __ldcg(&hb4[(size_t)(b0 + bb) * 128 + c]);
        }
        __syncthreads();

        // ---- matvec: W from registers, H via broadcast LDS ----
        unsigned long long a0x=0,a0y=0,a1x=0,a1y=0,a2x=0,a2y=0,a3x=0,a3y=0;
#pragma unroll
        for (int k = 0; k < 32; ++k) {
            int c = cbase + k;
            ulonglong2 x0 = H2[c];
            fma2(a0x, w[2*k], x0.x); fma2(a0y, w[2*k+1], x0.y);
            ulonglong2 x1 = H2[128 + c];
            fma2(a1x, w[2*k], x1.x); fma2(a1y, w[2*k+1], x1.y);
            ulonglong2 x2 = H2[256 + c];
            fma2(a2x, w[2*k], x2.x); fma2(a2y, w[2*k+1], x2.y);
            ulonglong2 x3 = H2[384 + c];
            fma2(a3x, w[2*k], x3.x); fma2(a3y, w[2*k+1], x3.y);
        }
        part[(js * 4 + 0) * 64 + h] = sum2(a0x) + sum2(a0y);
        part[(js * 4 + 1) * 64 + h] = sum2(a1x) + sum2(a1y);
        part[(js * 4 + 2) * 64 + h] = sum2(a2x) + sum2(a2y);
        part[(js * 4 + 3) * 64 + h] = sum2(a3x) + sum2(a3y);
        __syncthreads();

        // ---- reduce 4 partials, add xp, tanh, publish ----
        // final-stage thread: batch fb = js, h index fh = h
        float dot = part[(0 * 4 + js) * 64 + h]
                  + part[(1 * 4 + js) * 64 + h]
                  + part[(2 * 4 + js) * 64 + h]
                  + part[(3 * 4 + js) * 64 + h];
        float hn = tanhf(dot + xpv);
        g_hbuf[(size_t)((t + 1) & 1) * B * DIM + (size_t)(b0 + js) * DIM + hs0 + h] = hn;
        g_hid[((size_t)t * B + (b0 + js)) * DIM + hs0 + h] = hn;

        // ---- barrier among the 8 slice-CTAs of this group ----
        __threadfence();        // release
        __syncthreads();
        if (tid == 0) {
            unsigned* bar = &g_bar[t * RNN_GROUPS + g];
            atomicAdd(bar, 1u);
            while (*((volatile unsigned*)bar) < RNN_SLICES) { }
            __threadfence();    // acquire
        }
        __syncthreads();
    }
}

// =====================================================================
// Kernel 3: softmax over H (axis=1 of [B,H,T]) + transpose [t][b][h] -> [b][h][t]
// =====================================================================
__global__ __launch_bounds__(256) void softmax_kernel(float* __restrict__ out)
{
    __shared__ float tile[16][513];
    __shared__ float rinv[16];

    const int tid = threadIdx.x;
    const int bb  = blockIdx.y;
    const int t0  = blockIdx.x * 16;

#pragma unroll
    for (int it = 0; it < 32; ++it) {
        int f = it * 256 + tid;             // 0..8191
        int tt = f >> 9, hh = f & 511;
        tile[tt][hh] = __ldg(&g_hid[((size_t)(t0 + tt) * B + bb) * DIM + hh]);
    }
    __syncthreads();

    const int wid = tid >> 5, lane = tid & 31;
#pragma unroll
    for (int rr = 0; rr < 2; ++rr) {
        int tt = wid * 2 + rr;
        float m = -3.4e38f;
#pragma unroll
        for (int k = 0; k < 16; ++k) m = fmaxf(m, tile[tt][lane + 32 * k]);
#pragma unroll
        for (int off = 16; off >= 1; off >>= 1)
            m = fmaxf(m, __shfl_xor_sync(0xffffffffu, m, off));
        float s = 0.0f;
#pragma unroll
        for (int k = 0; k < 16; ++k) {
            float e = __expf(tile[tt][lane + 32 * k] - m);
            tile[tt][lane + 32 * k] = e;
            s += e;
        }
#pragma unroll
        for (int off = 16; off >= 1; off >>= 1)
            s += __shfl_xor_sync(0xffffffffu, s, off);
        if (lane == 0) rinv[tt] = 1.0f / s;
    }
    __syncthreads();

    const int hw  = tid >> 4;     // 0..15
    const int l16 = tid & 15;     // tt
#pragma unroll
    for (int it = 0; it < 32; ++it) {
        int hh = it * 16 + hw;
        float v = tile[l16][hh] * rinv[l16];
        out[((size_t)bb * DIM + hh) * T + t0 + l16] = v;
    }
}

// =====================================================================
extern "C" void kernel_launch(void* const* d_in, const int* in_sizes, int n_in,
                              void* d_out, int out_size)
{
    const int*   x    = (const int*)  d_in[0];
    const float* emb  = (const float*)d_in[1];
    const float* W_ih = (const float*)d_in[2];
    const float* W_hh = (const float*)d_in[3];
    const float* b_ih = (const float*)d_in[4];
    const float* b_hh = (const float*)d_in[5];
    float* out = (float*)d_out;

    void *p_hbuf, *p_bar;
    cudaGetSymbolAddress(&p_hbuf, g_hbuf);
    cudaGetSymbolAddress(&p_bar,  g_bar);
    cudaMemsetAsync(p_hbuf, 0, sizeof(float) * 2 * B * DIM);
    cudaMemsetAsync(p_bar,  0, sizeof(unsigned) * T * 16);

    // 1) input projection GEMM -> g_xp
    gemm_xp_kernel<<<dim3(DIM / GBN, (T * B) / GBM), 256>>>(x, emb, W_ih, b_ih, b_hh);

    // 2) persistent recurrence -> g_hid
    rnn_kernel<<<dim3(RNN_SLICES, RNN_GROUPS), 256>>>(W_hh);

    // 3) softmax over H + transpose -> out
    softmax_kernel<<<dim3(T / 16, B), 256>>>(out);
}

// round 6
// speedup vs baseline: 1.8625x; 1.6732x over previous
#include <cuda_runtime.h>
#include <cuda_bf16.h>
#include <cstdint>

// Problem constants
#define B      64
#define T      512
#define DIM    512
#define VOCAB  32000

// ---------------- device scratch (no allocation allowed) ----------------
__device__ float    g_xp [(size_t)T * B * DIM];   // [t][b][h]  67MB
__device__ float    g_hid[(size_t)T * B * DIM];   // [t][b][h]  67MB
__device__ float    g_hbuf[2 * B * DIM];          // double-buffered h state
__device__ unsigned g_bar[T * 16];                // per-step per-group barrier

// ---------------- packed fp32x2 FMA (Blackwell FFMA2) ----------------
__device__ __forceinline__ void fma2(unsigned long long &d,
                                     unsigned long long a,
                                     unsigned long long b) {
    asm("fma.rn.f32x2 %0, %1, %2, %0;" : "+l"(d) : "l"(a), "l"(b));
}
__device__ __forceinline__ float sum2(unsigned long long v) {
    return __uint_as_float((unsigned)v) + __uint_as_float((unsigned)(v >> 32));
}
__device__ __forceinline__ unsigned long long pack2(float a) {
    unsigned long long r;
    asm("mov.b64 %0, {%1, %1};" : "=l"(r) : "f"(a));
    return r;
}
__device__ __forceinline__ float lo32(unsigned long long v) {
    return __uint_as_float((unsigned)v);
}
__device__ __forceinline__ float hi32(unsigned long long v) {
    return __uint_as_float((unsigned)(v >> 32));
}

// =====================================================================
// Kernel 1: xp[t][b][h] = emb[x[b][t]] . W_ih[h] + b_ih[h] + b_hh[h]
// 128x128x16 tiles, 256 threads, 8x8 register blocking, f32x2 accumulate,
// DOUBLE-BUFFERED smem (1 sync per K-tile, LDG overlapped with compute).
// =====================================================================
#define GBM 128
#define GBN 128
#define GBK 16
#define GLD 132   // k-major row stride (floats), padded

__global__ __launch_bounds__(256) void gemm_xp_kernel(
    const int* __restrict__ x, const float* __restrict__ emb,
    const float* __restrict__ W_ih, const float* __restrict__ b_ih,
    const float* __restrict__ b_hh)
{
    __shared__ float As[2][GBK][GLD];   // [buf][k][m]
    __shared__ float Bs[2][GBK][GLD];   // [buf][k][n]
    __shared__ int   idxs[GBM];
    __shared__ float bias[GBN];

    const int tid = threadIdx.x;
    const int tx = tid & 15, ty = tid >> 4;
    const int m0 = blockIdx.y * GBM;        // m = t*64 + b
    const int n0 = blockIdx.x * GBN;

    if (tid < GBM) {
        int m = m0 + tid;
        int bb = m & 63, tt = m >> 6;
        idxs[tid] = x[bb * T + tt];
        bias[tid] = b_ih[n0 + tid] + b_hh[n0 + tid];
    }
    __syncthreads();

    unsigned long long acc[8][4];
#pragma unroll
    for (int i = 0; i < 8; ++i)
#pragma unroll
        for (int j = 0; j < 4; ++j) acc[i][j] = 0ull;

    const float4* emb4 = reinterpret_cast<const float4*>(emb);
    const float4* wih4 = reinterpret_cast<const float4*>(W_ih);

    // per-thread global-load coordinates (2 float4 from each of A,B per tile)
    int mmv[2], kqv[2];
#pragma unroll
    for (int r = 0; r < 2; ++r) {
        int f = r * 256 + tid;
        mmv[r] = f >> 2; kqv[r] = f & 3;
    }

    float4 av[2], bv[2];
    // prologue: load tile 0
#pragma unroll
    for (int r = 0; r < 2; ++r) {
        av[r] = __ldg(&emb4[(size_t)idxs[mmv[r]] * (DIM / 4) + kqv[r]]);
        bv[r] = __ldg(&wih4[(size_t)(n0 + mmv[r]) * (DIM / 4) + kqv[r]]);
    }
#pragma unroll
    for (int r = 0; r < 2; ++r) {
        int mm = mmv[r], kc = kqv[r] * 4;
        As[0][kc + 0][mm] = av[r].x; As[0][kc + 1][mm] = av[r].y;
        As[0][kc + 2][mm] = av[r].z; As[0][kc + 3][mm] = av[r].w;
        Bs[0][kc + 0][mm] = bv[r].x; Bs[0][kc + 1][mm] = bv[r].y;
        Bs[0][kc + 2][mm] = bv[r].z; Bs[0][kc + 3][mm] = bv[r].w;
    }
    __syncthreads();

    const int NT = DIM / GBK;   // 32 K-tiles
    for (int kt = 0; kt < NT; ++kt) {
        const int cur = kt & 1;
        // issue global loads for next tile (latency hidden behind compute)
        if (kt < NT - 1) {
            int kq = (kt + 1) * 4;
#pragma unroll
            for (int r = 0; r < 2; ++r) {
                av[r] = __ldg(&emb4[(size_t)idxs[mmv[r]] * (DIM / 4) + kq + kqv[r]]);
                bv[r] = __ldg(&wih4[(size_t)(n0 + mmv[r]) * (DIM / 4) + kq + kqv[r]]);
            }
        }

#pragma unroll
        for (int kk = 0; kk < GBK; ++kk) {
            float4 a0 = *reinterpret_cast<const float4*>(&As[cur][kk][ty * 4]);
            float4 a1 = *reinterpret_cast<const float4*>(&As[cur][kk][64 + ty * 4]);
            float4 b0 = *reinterpret_cast<const float4*>(&Bs[cur][kk][tx * 4]);
            float4 b1 = *reinterpret_cast<const float4*>(&Bs[cur][kk][64 + tx * 4]);
            ulonglong2 bp0 = *reinterpret_cast<ulonglong2*>(&b0);
            ulonglong2 bp1 = *reinterpret_cast<ulonglong2*>(&b1);
            float avv[8] = {a0.x, a0.y, a0.z, a0.w, a1.x, a1.y, a1.z, a1.w};
#pragma unroll
            for (int i = 0; i < 8; ++i) {
                unsigned long long ap = pack2(avv[i]);
                fma2(acc[i][0], ap, bp0.x);
                fma2(acc[i][1], ap, bp0.y);
                fma2(acc[i][2], ap, bp1.x);
                fma2(acc[i][3], ap, bp1.y);
            }
        }

        if (kt < NT - 1) {
            const int nxt = 1 - cur;
#pragma unroll
            for (int r = 0; r < 2; ++r) {
                int mm = mmv[r], kc = kqv[r] * 4;
                As[nxt][kc + 0][mm] = av[r].x; As[nxt][kc + 1][mm] = av[r].y;
                As[nxt][kc + 2][mm] = av[r].z; As[nxt][kc + 3][mm] = av[r].w;
                Bs[nxt][kc + 0][mm] = bv[r].x; Bs[nxt][kc + 1][mm] = bv[r].y;
                Bs[nxt][kc + 2][mm] = bv[r].z; Bs[nxt][kc + 3][mm] = bv[r].w;
            }
            __syncthreads();
        }
    }

    float4 bs0 = *reinterpret_cast<const float4*>(&bias[tx * 4]);
    float4 bs1 = *reinterpret_cast<const float4*>(&bias[64 + tx * 4]);
#pragma unroll
    for (int i = 0; i < 8; ++i) {
        int m = m0 + ((i < 4) ? (ty * 4 + i) : (64 + ty * 4 + (i - 4)));
        float4 o0, o1;
        o0.x = lo32(acc[i][0]) + bs0.x;  o0.y = hi32(acc[i][0]) + bs0.y;
        o0.z = lo32(acc[i][1]) + bs0.z;  o0.w = hi32(acc[i][1]) + bs0.w;
        o1.x = lo32(acc[i][2]) + bs1.x;  o1.y = hi32(acc[i][2]) + bs1.y;
        o1.z = lo32(acc[i][3]) + bs1.z;  o1.w = hi32(acc[i][3]) + bs1.w;
        *reinterpret_cast<float4*>(&g_xp[(size_t)m * DIM + n0 + tx * 4])      = o0;
        *reinterpret_cast<float4*>(&g_xp[(size_t)m * DIM + n0 + 64 + tx * 4]) = o1;
    }
}

// =====================================================================
// Kernel 2: persistent RNN recurrence. W_hh resident in REGISTERS.
// Grid: (8 h-slices, 16 batch-groups) = 128 CTAs, all co-resident.
// 512 threads/CTA: thread (h=tid&63, js=tid>>6) owns
// W_hh[hs0+h][js*64 : js*64+64] in 32 f32x2 registers (~110 regs total,
// 16 warps for latency hiding). js is warp-uniform -> H smem reads are
// broadcast LDS.128.
// Barrier: bar.sync -> tid0 red.release.gpu + ld.acquire.gpu poll.
// g_hid store is AFTER the barrier (kept out of the release set).
// =====================================================================
#define RNN_GROUPS 16
#define RNN_SLICES 8
#define RNN_B 4
#define RNN_H 64

__global__ __launch_bounds__(512, 1) void rnn_kernel(const float* __restrict__ W_hh)
{
    __shared__ float hsm[RNN_B * DIM];            // 8KB: h state [b][j]
    __shared__ float part[8 * RNN_B * RNN_H];     // 8KB: [js][b][h]

    const int tid   = threadIdx.x;
    const int slice = blockIdx.x;
    const int g     = blockIdx.y;
    const int hs0   = slice * RNN_H;
    const int b0    = g * RNN_B;
    const int h     = tid & 63;
    const int js    = tid >> 6;      // 0..7, warp-uniform

    // --- this thread's W segment: 64 floats = 32 f32x2 regs ---
    unsigned long long w[32];
    {
        const float4* Wg4 = reinterpret_cast<const float4*>(W_hh)
                            + (size_t)(hs0 + h) * (DIM / 4) + js * 16;
#pragma unroll
        for (int k = 0; k < 16; ++k) {
            float4 v = __ldg(&Wg4[k]);
            ulonglong2 p = *reinterpret_cast<ulonglong2*>(&v);
            w[2 * k]     = p.x;
            w[2 * k + 1] = p.y;
        }
    }

    const ulonglong2* H2 = reinterpret_cast<const ulonglong2*>(hsm);  // [b*128 + c]
    float4* hsm4 = reinterpret_cast<float4*>(hsm);
    const int cb = js * 16;
    const int ob = js & 3;          // output batch for tid<256 (== js there)

    __syncthreads();

    float hid_keep = 0.0f;
    for (int t = 0; t < T; ++t) {
        // ---- prefetch xp for this thread's output element ----
        float xpv = 0.0f;
        if (tid < 256)
            xpv = __ldg(&g_xp[((size_t)t * B + (b0 + ob)) * DIM + hs0 + h]);

        // ---- load h_prev (L2-coherent) into smem: 512 x float4 ----
        {
            const float4* hb4 = reinterpret_cast<const float4*>(g_hbuf)
                                + (size_t)(t & 1) * (B * DIM / 4);
            int bb = tid >> 7, c = tid & 127;
            hsm4[bb * 128 + c] = __ldcg(&hb4[(size_t)(b0 + bb) * 128 + c]);
        }
        __syncthreads();

        // ---- matvec: W from registers, H via broadcast LDS ----
        unsigned long long a0x=0,a0y=0,a1x=0,a1y=0,a2x=0,a2y=0,a3x=0,a3y=0;
#pragma unroll
        for (int k = 0; k < 16; ++k) {
            int c = cb + k;
            ulonglong2 x0 = H2[c];
            fma2(a0x, w[2*k], x0.x); fma2(a0y, w[2*k+1], x0.y);
            ulonglong2 x1 = H2[128 + c];
            fma2(a1x, w[2*k], x1.x); fma2(a1y, w[2*k+1], x1.y);
            ulonglong2 x2 = H2[256 + c];
            fma2(a2x, w[2*k], x2.x); fma2(a2y, w[2*k+1], x2.y);
            ulonglong2 x3 = H2[384 + c];
            fma2(a3x, w[2*k], x3.x); fma2(a3y, w[2*k+1], x3.y);
        }
        part[(js * 4 + 0) * 64 + h] = sum2(a0x) + sum2(a0y);
        part[(js * 4 + 1) * 64 + h] = sum2(a1x) + sum2(a1y);
        part[(js * 4 + 2) * 64 + h] = sum2(a2x) + sum2(a2y);
        part[(js * 4 + 3) * 64 + h] = sum2(a3x) + sum2(a3y);
        __syncthreads();

        // ---- reduce 8 partials, add xp, tanh, publish exchange value ----
        if (tid < 256) {
            float dot = 0.0f;
#pragma unroll
            for (int s = 0; s < 8; ++s) dot += part[(s * 4 + ob) * 64 + h];
            float hn = tanhf(dot + xpv);
            g_hbuf[(size_t)((t + 1) & 1) * B * DIM
                   + (size_t)(b0 + ob) * DIM + hs0 + h] = hn;
            hid_keep = hn;
        }
        __syncthreads();   // all g_hbuf stores happen-before tid0's release

        // ---- inter-CTA barrier: tid0-only release arrive + acquire poll ----
        if (tid == 0) {
            unsigned* bar = &g_bar[t * RNN_GROUPS + g];
            asm volatile("red.release.gpu.global.add.u32 [%0], %1;"
                         :: "l"(bar), "r"(1u) : "memory");
            unsigned v;
            do {
                asm volatile("ld.acquire.gpu.global.u32 %0, [%1];"
                             : "=r"(v) : "l"(bar) : "memory");
            } while (v < RNN_SLICES);
        }
        __syncthreads();

        // ---- lazy history store (off the critical exchange path) ----
        if (tid < 256)
            g_hid[((size_t)t * B + (b0 + ob)) * DIM + hs0 + h] = hid_keep;
    }
}

// =====================================================================
// Kernel 3: softmax over H (axis=1 of [B,H,T]) + transpose [t][b][h] -> [b][h][t]
// =====================================================================
__global__ __launch_bounds__(256) void softmax_kernel(float* __restrict__ out)
{
    __shared__ float tile[16][513];
    __shared__ float rinv[16];

    const int tid = threadIdx.x;
    const int bb  = blockIdx.y;
    const int t0  = blockIdx.x * 16;

#pragma unroll
    for (int it = 0; it < 32; ++it) {
        int f = it * 256 + tid;             // 0..8191
        int tt = f >> 9, hh = f & 511;
        tile[tt][hh] = __ldg(&g_hid[((size_t)(t0 + tt) * B + bb) * DIM + hh]);
    }
    __syncthreads();

    const int wid = tid >> 5, lane = tid & 31;
#pragma unroll
    for (int rr = 0; rr < 2; ++rr) {
        int tt = wid * 2 + rr;
        float m = -3.4e38f;
#pragma unroll
        for (int k = 0; k < 16; ++k) m = fmaxf(m, tile[tt][lane + 32 * k]);
#pragma unroll
        for (int off = 16; off >= 1; off >>= 1)
            m = fmaxf(m, __shfl_xor_sync(0xffffffffu, m, off));
        float s = 0.0f;
#pragma unroll
        for (int k = 0; k < 16; ++k) {
            float e = __expf(tile[tt][lane + 32 * k] - m);
            tile[tt][lane + 32 * k] = e;
            s += e;
        }
#pragma unroll
        for (int off = 16; off >= 1; off >>= 1)
            s += __shfl_xor_sync(0xffffffffu, s, off);
        if (lane == 0) rinv[tt] = 1.0f / s;
    }
    __syncthreads();

    const int hw  = tid >> 4;     // 0..15
    const int l16 = tid & 15;     // tt
#pragma unroll
    for (int it = 0; it < 32; ++it) {
        int hh = it * 16 + hw;
        float v = tile[l16][hh] * rinv[l16];
        out[((size_t)bb * DIM + hh) * T + t0 + l16] = v;
    }
}

// =====================================================================
extern "C" void kernel_launch(void* const* d_in, const int* in_sizes, int n_in,
                              void* d_out, int out_size)
{
    const int*   x    = (const int*)  d_in[0];
    const float* emb  = (const float*)d_in[1];
    const float* W_ih = (const float*)d_in[2];
    const float* W_hh = (const float*)d_in[3];
    const float* b_ih = (const float*)d_in[4];
    const float* b_hh = (const float*)d_in[5];
    float* out = (float*)d_out;

    void *p_hbuf, *p_bar;
    cudaGetSymbolAddress(&p_hbuf, g_hbuf);
    cudaGetSymbolAddress(&p_bar,  g_bar);
    cudaMemsetAsync(p_hbuf, 0, sizeof(float) * 2 * B * DIM);
    cudaMemsetAsync(p_bar,  0, sizeof(unsigned) * T * 16);

    // 1) input projection GEMM -> g_xp
    gemm_xp_kernel<<<dim3(DIM / GBN, (T * B) / GBM), 256>>>(x, emb, W_ih, b_ih, b_hh);

    // 2) persistent recurrence -> g_hid
    rnn_kernel<<<dim3(RNN_SLICES, RNN_GROUPS), 512>>>(W_hh);

    // 3) softmax over H + transpose -> out
    softmax_kernel<<<dim3(T / 16, B), 256>>>(out);
}

// round 7
// speedup vs baseline: 1.9919x; 1.0695x over previous
#include <cuda_runtime.h>
#include <cuda_bf16.h>
#include <cstdint>

// Problem constants
#define B      64
#define T      512
#define DIM    512
#define VOCAB  32000

// ---------------- device scratch (no allocation allowed) ----------------
__device__ float    g_xp [(size_t)T * B * DIM];   // [t][b][h]  67MB
__device__ float    g_hid[(size_t)T * B * DIM];   // [t][b][h]  67MB
__device__ float    g_hbuf[2 * B * DIM];          // double-buffered h state
__device__ unsigned g_flag[(size_t)T * 8 * 16 * 8];  // per (t,slice,group), 32B stride

// ---------------- packed fp32x2 FMA (Blackwell FFMA2) ----------------
__device__ __forceinline__ void fma2(unsigned long long &d,
                                     unsigned long long a,
                                     unsigned long long b) {
    asm("fma.rn.f32x2 %0, %1, %2, %0;" : "+l"(d) : "l"(a), "l"(b));
}
__device__ __forceinline__ float sum2(unsigned long long v) {
    return __uint_as_float((unsigned)v) + __uint_as_float((unsigned)(v >> 32));
}
__device__ __forceinline__ unsigned long long pack2(float a) {
    unsigned long long r;
    asm("mov.b64 %0, {%1, %1};" : "=l"(r) : "f"(a));
    return r;
}
__device__ __forceinline__ float lo32(unsigned long long v) {
    return __uint_as_float((unsigned)v);
}
__device__ __forceinline__ float hi32(unsigned long long v) {
    return __uint_as_float((unsigned)(v >> 32));
}

// =====================================================================
// Kernel 1: xp[t][b][h] = emb[x[b][t]] . W_ih[h] + b_ih[h] + b_hh[h]
// 128x128x16 tiles, 256 threads, 8x8 register blocking, f32x2 accumulate,
// double-buffered smem (1 sync per K-tile, LDG overlapped with compute).
// =====================================================================
#define GBM 128
#define GBN 128
#define GBK 16
#define GLD 132   // k-major row stride (floats), padded

__global__ __launch_bounds__(256) void gemm_xp_kernel(
    const int* __restrict__ x, const float* __restrict__ emb,
    const float* __restrict__ W_ih, const float* __restrict__ b_ih,
    const float* __restrict__ b_hh)
{
    __shared__ float As[2][GBK][GLD];   // [buf][k][m]
    __shared__ float Bs[2][GBK][GLD];   // [buf][k][n]
    __shared__ int   idxs[GBM];
    __shared__ float bias[GBN];

    const int tid = threadIdx.x;
    const int tx = tid & 15, ty = tid >> 4;
    const int m0 = blockIdx.y * GBM;        // m = t*64 + b
    const int n0 = blockIdx.x * GBN;

    if (tid < GBM) {
        int m = m0 + tid;
        int bb = m & 63, tt = m >> 6;
        idxs[tid] = x[bb * T + tt];
        bias[tid] = b_ih[n0 + tid] + b_hh[n0 + tid];
    }
    __syncthreads();

    unsigned long long acc[8][4];
#pragma unroll
    for (int i = 0; i < 8; ++i)
#pragma unroll
        for (int j = 0; j < 4; ++j) acc[i][j] = 0ull;

    const float4* emb4 = reinterpret_cast<const float4*>(emb);
    const float4* wih4 = reinterpret_cast<const float4*>(W_ih);

    int mmv[2], kqv[2];
#pragma unroll
    for (int r = 0; r < 2; ++r) {
        int f = r * 256 + tid;
        mmv[r] = f >> 2; kqv[r] = f & 3;
    }

    float4 av[2], bv[2];
#pragma unroll
    for (int r = 0; r < 2; ++r) {
        av[r] = __ldg(&emb4[(size_t)idxs[mmv[r]] * (DIM / 4) + kqv[r]]);
        bv[r] = __ldg(&wih4[(size_t)(n0 + mmv[r]) * (DIM / 4) + kqv[r]]);
    }
#pragma unroll
    for (int r = 0; r < 2; ++r) {
        int mm = mmv[r], kc = kqv[r] * 4;
        As[0][kc + 0][mm] = av[r].x; As[0][kc + 1][mm] = av[r].y;
        As[0][kc + 2][mm] = av[r].z; As[0][kc + 3][mm] = av[r].w;
        Bs[0][kc + 0][mm] = bv[r].x; Bs[0][kc + 1][mm] = bv[r].y;
        Bs[0][kc + 2][mm] = bv[r].z; Bs[0][kc + 3][mm] = bv[r].w;
    }
    __syncthreads();

    const int NT = DIM / GBK;   // 32 K-tiles
    for (int kt = 0; kt < NT; ++kt) {
        const int cur = kt & 1;
        if (kt < NT - 1) {
            int kq = (kt + 1) * 4;
#pragma unroll
            for (int r = 0; r < 2; ++r) {
                av[r] = __ldg(&emb4[(size_t)idxs[mmv[r]] * (DIM / 4) + kq + kqv[r]]);
                bv[r] = __ldg(&wih4[(size_t)(n0 + mmv[r]) * (DIM / 4) + kq + kqv[r]]);
            }
        }

#pragma unroll
        for (int kk = 0; kk < GBK; ++kk) {
            float4 a0 = *reinterpret_cast<const float4*>(&As[cur][kk][ty * 4]);
            float4 a1 = *reinterpret_cast<const float4*>(&As[cur][kk][64 + ty * 4]);
            float4 b0 = *reinterpret_cast<const float4*>(&Bs[cur][kk][tx * 4]);
            float4 b1 = *reinterpret_cast<const float4*>(&Bs[cur][kk][64 + tx * 4]);
            ulonglong2 bp0 = *reinterpret_cast<ulonglong2*>(&b0);
            ulonglong2 bp1 = *reinterpret_cast<ulonglong2*>(&b1);
            float avv[8] = {a0.x, a0.y, a0.z, a0.w, a1.x, a1.y, a1.z, a1.w};
#pragma unroll
            for (int i = 0; i < 8; ++i) {
                unsigned long long ap = pack2(avv[i]);
                fma2(acc[i][0], ap, bp0.x);
                fma2(acc[i][1], ap, bp0.y);
                fma2(acc[i][2], ap, bp1.x);
                fma2(acc[i][3], ap, bp1.y);
            }
        }

        if (kt < NT - 1) {
            const int nxt = 1 - cur;
#pragma unroll
            for (int r = 0; r < 2; ++r) {
                int mm = mmv[r], kc = kqv[r] * 4;
                As[nxt][kc + 0][mm] = av[r].x; As[nxt][kc + 1][mm] = av[r].y;
                As[nxt][kc + 2][mm] = av[r].z; As[nxt][kc + 3][mm] = av[r].w;
                Bs[nxt][kc + 0][mm] = bv[r].x; Bs[nxt][kc + 1][mm] = bv[r].y;
                Bs[nxt][kc + 2][mm] = bv[r].z; Bs[nxt][kc + 3][mm] = bv[r].w;
            }
            __syncthreads();
        }
    }

    float4 bs0 = *reinterpret_cast<const float4*>(&bias[tx * 4]);
    float4 bs1 = *reinterpret_cast<const float4*>(&bias[64 + tx * 4]);
#pragma unroll
    for (int i = 0; i < 8; ++i) {
        int m = m0 + ((i < 4) ? (ty * 4 + i) : (64 + ty * 4 + (i - 4)));
        float4 o0, o1;
        o0.x = lo32(acc[i][0]) + bs0.x;  o0.y = hi32(acc[i][0]) + bs0.y;
        o0.z = lo32(acc[i][1]) + bs0.z;  o0.w = hi32(acc[i][1]) + bs0.w;
        o1.x = lo32(acc[i][2]) + bs1.x;  o1.y = hi32(acc[i][2]) + bs1.y;
        o1.z = lo32(acc[i][3]) + bs1.z;  o1.w = hi32(acc[i][3]) + bs1.w;
        *reinterpret_cast<float4*>(&g_xp[(size_t)m * DIM + n0 + tx * 4])      = o0;
        *reinterpret_cast<float4*>(&g_xp[(size_t)m * DIM + n0 + 64 + tx * 4]) = o1;
    }
}

// =====================================================================
// Kernel 2: persistent RNN recurrence, PER-SLICE flag gating.
// Grid: (8 slices, 16 groups) = 128 co-resident CTAs, 512 threads.
// Thread (h=tid&63, js=tid>>6) owns W_hh[hs0+h][js*64 .. +64) in 32 f32x2
// registers. Each js-group (64 threads, 2 warps) depends on exactly ONE
// producer slice -> it waits only that slice's per-step flag, loads the
// 1KB slice from L2 into smem, then computes. Early slices overlap with
// late producers (skew + latency hidden behind compute).
// =====================================================================
#define RNN_GROUPS 16
#define RNN_SLICES 8
#define RNN_B 4
#define RNN_H 64

__device__ __forceinline__ unsigned flag_idx(int t, int s, int g) {
    return (unsigned)(((t * 8 + s) * 16 + g) * 8);
}

__global__ __launch_bounds__(512, 1) void rnn_kernel(const float* __restrict__ W_hh)
{
    __shared__ float hsm[2][RNN_B * DIM];         // 16KB double-buffered h
    __shared__ float part[8 * RNN_B * RNN_H];     // 8KB: [js][b][h]

    const int tid   = threadIdx.x;
    const int slice = blockIdx.x;
    const int g     = blockIdx.y;
    const int hs0   = slice * RNN_H;
    const int b0    = g * RNN_B;
    const int h     = tid & 63;
    const int js    = tid >> 6;      // 0..7, warp-uniform
    const int ob    = js & 3;        // output batch for tid<256

    // --- this thread's W segment: 64 floats = 32 f32x2 regs ---
    unsigned long long w[32];
    {
        const float4* Wg4 = reinterpret_cast<const float4*>(W_hh)
                            + (size_t)(hs0 + h) * (DIM / 4) + js * 16;
#pragma unroll
        for (int k = 0; k < 16; ++k) {
            float4 v = __ldg(&Wg4[k]);
            ulonglong2 p = *reinterpret_cast<ulonglong2*>(&v);
            w[2 * k]     = p.x;
            w[2 * k + 1] = p.y;
        }
    }

    // zero hsm[0] (h(0) = 0)
#pragma unroll
    for (int r = 0; r < 4; ++r) hsm[0][r * 512 + tid] = 0.0f;

    // per-js slice-load coordinates: 64 threads load 64 float4 (4 batches x 16)
    const int lb = h >> 4;          // batch 0..3
    const int lc = (h & 15) * 4;    // float offset within 64-col slice
    const int cb = js * 16;         // ulonglong2 column base

    __syncthreads();

    float hid_keep = 0.0f;
    for (int t = 0; t < T; ++t) {
        const int cur = t & 1;
        // ---- prefetch xp for this thread's output element ----
        float xpv = 0.0f;
        if (tid < 256)
            xpv = __ldg(&g_xp[((size_t)t * B + (b0 + ob)) * DIM + hs0 + h]);

        // ---- per-js gate: wait slice js's flag, pull 1KB slice from L2 ----
        if (t > 0) {
            const unsigned* fp = &g_flag[flag_idx(t, js, g)];
            unsigned v;
            do {
                asm volatile("ld.acquire.gpu.global.u32 %0, [%1];"
                             : "=r"(v) : "l"(fp) : "memory");
            } while (!v);
            // load h[b0+lb][js*64 + lc .. +4) -> hsm[cur]
            const float4* src = reinterpret_cast<const float4*>(
                &g_hbuf[(size_t)cur * B * DIM + (size_t)(b0 + lb) * DIM + js * 64 + lc]);
            float4 hv = __ldcg(src);
            *reinterpret_cast<float4*>(&hsm[cur][lb * 512 + js * 64 + lc]) = hv;
            // join the 64 threads of this js-group (named barrier js+1)
            asm volatile("bar.sync %0, %1;" :: "r"(js + 1), "r"(64) : "memory");
        }

        // ---- matvec: W from registers, H via broadcast LDS ----
        const ulonglong2* H2 = reinterpret_cast<const ulonglong2*>(hsm[cur]);
        unsigned long long a0x=0,a0y=0,a1x=0,a1y=0,a2x=0,a2y=0,a3x=0,a3y=0;
#pragma unroll
        for (int k = 0; k < 16; ++k) {
            int c = cb + k;
            ulonglong2 x0 = H2[c];
            fma2(a0x, w[2*k], x0.x); fma2(a0y, w[2*k+1], x0.y);
            ulonglong2 x1 = H2[128 + c];
            fma2(a1x, w[2*k], x1.x); fma2(a1y, w[2*k+1], x1.y);
            ulonglong2 x2 = H2[256 + c];
            fma2(a2x, w[2*k], x2.x); fma2(a2y, w[2*k+1], x2.y);
            ulonglong2 x3 = H2[384 + c];
            fma2(a3x, w[2*k], x3.x); fma2(a3y, w[2*k+1], x3.y);
        }
        part[(js * 4 + 0) * 64 + h] = sum2(a0x) + sum2(a0y);
        part[(js * 4 + 1) * 64 + h] = sum2(a1x) + sum2(a1y);
        part[(js * 4 + 2) * 64 + h] = sum2(a2x) + sum2(a2y);
        part[(js * 4 + 3) * 64 + h] = sum2(a3x) + sum2(a3y);
        __syncthreads();

        // ---- reduce 8 partials, add xp, tanh, publish exchange value ----
        if (tid < 256) {
            float dot = 0.0f;
#pragma unroll
            for (int s = 0; s < 8; ++s) dot += part[(s * 4 + ob) * 64 + h];
            float hn = tanhf(dot + xpv);
            hid_keep = hn;
            if (t < T - 1)
                g_hbuf[(size_t)((t + 1) & 1) * B * DIM
                       + (size_t)(b0 + ob) * DIM + hs0 + h] = hn;
        }
        __syncthreads();   // all h stores happen-before tid0's release

        // ---- release this slice's flag for step t+1 ----
        if (t < T - 1 && tid == 0) {
            unsigned* fp = &g_flag[flag_idx(t + 1, slice, g)];
            asm volatile("st.release.gpu.global.u32 [%0], %1;"
                         :: "l"(fp), "r"(1u) : "memory");
        }

        // ---- lazy history store (off the critical exchange path) ----
        if (tid < 256)
            g_hid[((size_t)t * B + (b0 + ob)) * DIM + hs0 + h] = hid_keep;
    }
}

// =====================================================================
// Kernel 3: softmax over H (axis=1 of [B,H,T]) + transpose [t][b][h] -> [b][h][t]
// =====================================================================
__global__ __launch_bounds__(256) void softmax_kernel(float* __restrict__ out)
{
    __shared__ float tile[16][513];
    __shared__ float rinv[16];

    const int tid = threadIdx.x;
    const int bb  = blockIdx.y;
    const int t0  = blockIdx.x * 16;

#pragma unroll
    for (int it = 0; it < 32; ++it) {
        int f = it * 256 + tid;             // 0..8191
        int tt = f >> 9, hh = f & 511;
        tile[tt][hh] = __ldg(&g_hid[((size_t)(t0 + tt) * B + bb) * DIM + hh]);
    }
    __syncthreads();

    const int wid = tid >> 5, lane = tid & 31;
#pragma unroll
    for (int rr = 0; rr < 2; ++rr) {
        int tt = wid * 2 + rr;
        float m = -3.4e38f;
#pragma unroll
        for (int k = 0; k < 16; ++k) m = fmaxf(m, tile[tt][lane + 32 * k]);
#pragma unroll
        for (int off = 16; off >= 1; off >>= 1)
            m = fmaxf(m, __shfl_xor_sync(0xffffffffu, m, off));
        float s = 0.0f;
#pragma unroll
        for (int k = 0; k < 16; ++k) {
            float e = __expf(tile[tt][lane + 32 * k] - m);
            tile[tt][lane + 32 * k] = e;
            s += e;
        }
#pragma unroll
        for (int off = 16; off >= 1; off >>= 1)
            s += __shfl_xor_sync(0xffffffffu, s, off);
        if (lane == 0) rinv[tt] = 1.0f / s;
    }
    __syncthreads();

    const int hw  = tid >> 4;     // 0..15
    const int l16 = tid & 15;     // tt
#pragma unroll
    for (int it = 0; it < 32; ++it) {
        int hh = it * 16 + hw;
        float v = tile[l16][hh] * rinv[l16];
        out[((size_t)bb * DIM + hh) * T + t0 + l16] = v;
    }
}

// =====================================================================
extern "C" void kernel_launch(void* const* d_in, const int* in_sizes, int n_in,
                              void* d_out, int out_size)
{
    const int*   x    = (const int*)  d_in[0];
    const float* emb  = (const float*)d_in[1];
    const float* W_ih = (const float*)d_in[2];
    const float* W_hh = (const float*)d_in[3];
    const float* b_ih = (const float*)d_in[4];
    const float* b_hh = (const float*)d_in[5];
    float* out = (float*)d_out;

    void* p_flag;
    cudaGetSymbolAddress(&p_flag, g_flag);
    cudaMemsetAsync(p_flag, 0, sizeof(unsigned) * (size_t)T * 8 * 16 * 8);

    // 1) input projection GEMM -> g_xp
    gemm_xp_kernel<<<dim3(DIM / GBN, (T * B) / GBM), 256>>>(x, emb, W_ih, b_ih, b_hh);

    // 2) persistent recurrence -> g_hid
    rnn_kernel<<<dim3(RNN_SLICES, RNN_GROUPS), 512>>>(W_hh);

    // 3) softmax over H + transpose -> out
    softmax_kernel<<<dim3(T / 16, B), 256>>>(out);
}